// round 2
// baseline (speedup 1.0000x reference)
#include <cuda_runtime.h>

// Ring attention == full attention per (b,h): every query group g attends the
// same 4096-key KV set (exact LSE merge makes rotation order irrelevant).
// Flash-attention SIMT fp32 baseline.

#define GDIM 4
#define BDIM 2
#define HDIM 16
#define SDIM 1024
#define DDIM 64
#define QT 64
#define KT 64
#define PITCH 68   // floats; 272B rows -> 16B aligned, bank-conflict skew

__global__ __launch_bounds__(256) void ring_attn_fwd(
    const float* __restrict__ q,
    const float* __restrict__ k,
    const float* __restrict__ v,
    float* __restrict__ out)
{
    extern __shared__ float smem[];
    float* Qs = smem;                      // [DDIM][PITCH]  transposed: Qs[d][row], pre-scaled
    float* Ks = Qs + DDIM * PITCH;         // [DDIM][PITCH]  transposed: Ks[d][col]
    float* Ps = Ks + DDIM * PITCH;         // [KT][PITCH]    transposed: Ps[kcol][row]
    float* Vs = Ps + KT * PITCH;           // [KT][DDIM]     natural:    Vs[krow][d]

    const int tid = threadIdx.x;
    const int tx = tid & 15;               // output-dim / key-col tile index
    const int ty = tid >> 4;               // query-row tile index

    const int g  = blockIdx.x >> 4;        // ring slot of the query block
    const int qt = blockIdx.x & 15;        // q tile within S
    const int bh = blockIdx.y;             // b*HDIM + h

    const size_t g_stride = (size_t)BDIM * HDIM * SDIM * DDIM;
    const size_t bh_off   = (size_t)bh * SDIM * DDIM;

    const float* qbase = q + (size_t)g * g_stride + bh_off + (size_t)qt * QT * DDIM;
    const float scale = 0.125f;            // 1/sqrt(64)

    // ---- load Q tile, transposed + pre-scaled ----
    #pragma unroll
    for (int jj = 0; jj < 4; jj++) {
        int vi  = tid + jj * 256;          // float4 index, 0..1023
        int row = vi >> 4;
        int d0  = (vi & 15) << 2;
        float4 q4 = *reinterpret_cast<const float4*>(qbase + (size_t)row * DDIM + d0);
        Qs[(d0 + 0) * PITCH + row] = q4.x * scale;
        Qs[(d0 + 1) * PITCH + row] = q4.y * scale;
        Qs[(d0 + 2) * PITCH + row] = q4.z * scale;
        Qs[(d0 + 3) * PITCH + row] = q4.w * scale;
    }

    float m[4], l[4], o[4][4];
    #pragma unroll
    for (int r = 0; r < 4; r++) {
        m[r] = -1e30f;
        l[r] = 0.0f;
        #pragma unroll
        for (int c = 0; c < 4; c++) o[r][c] = 0.0f;
    }

    for (int j = 0; j < GDIM; j++) {
        const float* kb = k + (size_t)j * g_stride + bh_off;
        const float* vb = v + (size_t)j * g_stride + bh_off;

        for (int kt = 0; kt < SDIM / KT; kt++) {
            // ---- load K tile (transposed) and V tile (natural) ----
            #pragma unroll
            for (int jj = 0; jj < 4; jj++) {
                int vi  = tid + jj * 256;
                int row = vi >> 4;
                int d0  = (vi & 15) << 2;
                const size_t goff = (size_t)(kt * KT + row) * DDIM + d0;
                float4 k4 = *reinterpret_cast<const float4*>(kb + goff);
                Ks[(d0 + 0) * PITCH + row] = k4.x;
                Ks[(d0 + 1) * PITCH + row] = k4.y;
                Ks[(d0 + 2) * PITCH + row] = k4.z;
                Ks[(d0 + 3) * PITCH + row] = k4.w;
                float4 v4 = *reinterpret_cast<const float4*>(vb + goff);
                *reinterpret_cast<float4*>(Vs + row * DDIM + d0) = v4;
            }
            __syncthreads();

            // ---- GEMM1: S = Q @ K^T (4x4 microtile per thread) ----
            float s4[4][4];
            #pragma unroll
            for (int r = 0; r < 4; r++)
                #pragma unroll
                for (int c = 0; c < 4; c++) s4[r][c] = 0.0f;

            #pragma unroll 8
            for (int d = 0; d < DDIM; d++) {
                float4 a  = *reinterpret_cast<float4*>(Qs + d * PITCH + ty * 4);
                float4 bb = *reinterpret_cast<float4*>(Ks + d * PITCH + tx * 4);
                float av[4] = {a.x, a.y, a.z, a.w};
                float bv[4] = {bb.x, bb.y, bb.z, bb.w};
                #pragma unroll
                for (int r = 0; r < 4; r++)
                    #pragma unroll
                    for (int c = 0; c < 4; c++)
                        s4[r][c] += av[r] * bv[c];
            }

            // ---- online softmax over this 64-key tile ----
            #pragma unroll
            for (int r = 0; r < 4; r++) {
                float mm = fmaxf(fmaxf(s4[r][0], s4[r][1]), fmaxf(s4[r][2], s4[r][3]));
                #pragma unroll
                for (int off = 1; off < 16; off <<= 1)
                    mm = fmaxf(mm, __shfl_xor_sync(0xffffffffu, mm, off));
                float mnew = fmaxf(m[r], mm);
                float corr = __expf(m[r] - mnew);
                m[r] = mnew;
                float rs = 0.0f;
                #pragma unroll
                for (int c = 0; c < 4; c++) {
                    float p = __expf(s4[r][c] - mnew);
                    s4[r][c] = p;
                    rs += p;
                }
                #pragma unroll
                for (int off = 1; off < 16; off <<= 1)
                    rs += __shfl_xor_sync(0xffffffffu, rs, off);
                l[r] = l[r] * corr + rs;
                #pragma unroll
                for (int c = 0; c < 4; c++) o[r][c] *= corr;
            }

            // ---- write P transposed: Ps[kcol][qrow], float4 along rows ----
            #pragma unroll
            for (int c = 0; c < 4; c++) {
                float4 pc = make_float4(s4[0][c], s4[1][c], s4[2][c], s4[3][c]);
                *reinterpret_cast<float4*>(Ps + (tx * 4 + c) * PITCH + ty * 4) = pc;
            }
            __syncthreads();

            // ---- GEMM2: O += P @ V ----
            #pragma unroll 8
            for (int kk = 0; kk < KT; kk++) {
                float4 a  = *reinterpret_cast<float4*>(Ps + kk * PITCH + ty * 4);
                float4 bb = *reinterpret_cast<float4*>(Vs + kk * DDIM + tx * 4);
                float av[4] = {a.x, a.y, a.z, a.w};
                float bv[4] = {bb.x, bb.y, bb.z, bb.w};
                #pragma unroll
                for (int r = 0; r < 4; r++)
                    #pragma unroll
                    for (int c = 0; c < 4; c++)
                        o[r][c] += av[r] * bv[c];
            }
            __syncthreads();   // protect Ks/Vs/Ps before next tile's loads
        }
    }

    // ---- epilogue: normalize and store ----
    float* obase = out + (size_t)g * g_stride + bh_off + (size_t)qt * QT * DDIM;
    #pragma unroll
    for (int r = 0; r < 4; r++) {
        float inv = 1.0f / l[r];
        float4 res = make_float4(o[r][0] * inv, o[r][1] * inv,
                                 o[r][2] * inv, o[r][3] * inv);
        *reinterpret_cast<float4*>(obase + (size_t)(ty * 4 + r) * DDIM + tx * 4) = res;
    }
}

extern "C" void kernel_launch(void* const* d_in, const int* in_sizes, int n_in,
                              void* d_out, int out_size)
{
    const float* q = (const float*)d_in[0];
    const float* k = (const float*)d_in[1];
    const float* v = (const float*)d_in[2];
    float* out = (float*)d_out;

    const int smem_bytes = (3 * DDIM * PITCH + KT * DDIM) * (int)sizeof(float); // 68608
    cudaFuncSetAttribute(ring_attn_fwd, cudaFuncAttributeMaxDynamicSharedMemorySize,
                         smem_bytes);

    dim3 grid(GDIM * (SDIM / QT), BDIM * HDIM);  // (64, 32)
    ring_attn_fwd<<<grid, 256, smem_bytes>>>(q, k, v, out);
}

// round 4
// speedup vs baseline: 3.9477x; 3.9477x over previous
#include <cuda_runtime.h>
#include <stdint.h>

// Ring attention == full attention per (b,h) (exact LSE merge is order-free).
// tf32 mma.sync flash attention. CTA = 256 thr = 8 warps, 128 q-rows (16/warp),
// KV tiles of 64 keys. Q fragments + O accumulators live in registers.
// GEMM1: S = Q·K^T  (B-frags from K smem, pitch 68 -> conflict-free)
// GEMM2: O += P·V   (P via per-warp smem round-trip, V pitch 72 -> conflict-free)

#define GDIM 4
#define BH   32
#define SDIM 1024
#define DDIM 64
#define MT   128
#define KT   64

#define KP 68   // K smem pitch (floats): bank = 4*key + d  -> lane-distinct
#define VP 72   // V smem pitch: bank = 8*key + d -> lane-distinct
#define PP 68   // P smem pitch

#define OFF_K 0
#define OFF_V (OFF_K + KT * KP)              // 4352
#define OFF_P (OFF_V + KT * VP)              // 8960
#define SMEM_FLOATS (OFF_P + 8 * 16 * PP)    // 17664 floats = 70656 B

static __device__ __forceinline__ uint32_t f2tf(float f) {
    uint32_t r;
    asm("cvt.rna.tf32.f32 %0, %1;" : "=r"(r) : "f"(f));
    return r;
}

static __device__ __forceinline__ void mma_tf32(float c[4], const uint32_t a[4],
                                                uint32_t b0, uint32_t b1) {
    asm volatile(
        "mma.sync.aligned.m16n8k8.row.col.f32.tf32.tf32.f32 "
        "{%0,%1,%2,%3}, {%4,%5,%6,%7}, {%8,%9}, {%0,%1,%2,%3};"
        : "+f"(c[0]), "+f"(c[1]), "+f"(c[2]), "+f"(c[3])
        : "r"(a[0]), "r"(a[1]), "r"(a[2]), "r"(a[3]), "r"(b0), "r"(b1));
}

__global__ __launch_bounds__(256, 2) void ring_attn_mma(
    const float* __restrict__ q,
    const float* __restrict__ k,
    const float* __restrict__ v,
    float* __restrict__ out)
{
    extern __shared__ float sm[];
    uint32_t* Ks = (uint32_t*)(sm + OFF_K);
    uint32_t* Vs = (uint32_t*)(sm + OFF_V);

    const int tid  = threadIdx.x;
    const int warp = tid >> 5;
    const int lane = tid & 31;
    const int tg   = lane >> 2;   // 0..7  (row group / n group)
    const int tl   = lane & 3;    // 0..3  (k lane / col group)

    float*    Pw = sm + OFF_P + warp * 16 * PP;   // per-warp P buffer
    uint32_t* Pu = (uint32_t*)Pw;

    const int g  = blockIdx.x >> 3;
    const int qt = blockIdx.x & 7;
    const int bh = blockIdx.y;
    const size_t GSTRIDE = (size_t)BH * SDIM * DDIM;
    const size_t bhoff   = (size_t)bh * SDIM * DDIM;

    // ---- Q fragments: held in registers for the whole kernel ----
    // a0=(r,c) a1=(r+8,c) a2=(r,c+4) a3=(r+8,c+4); r=tg, c=tl within k-chunk
    uint32_t aQ[8][4];
    {
        const float* q0 = q + (size_t)g * GSTRIDE + bhoff
                        + (size_t)(qt * MT + warp * 16 + tg) * DDIM;
        const float* q1 = q0 + 8 * DDIM;
        #pragma unroll
        for (int kc = 0; kc < 8; kc++) {
            aQ[kc][0] = f2tf(q0[kc * 8 + tl]     * 0.125f);
            aQ[kc][1] = f2tf(q1[kc * 8 + tl]     * 0.125f);
            aQ[kc][2] = f2tf(q0[kc * 8 + tl + 4] * 0.125f);
            aQ[kc][3] = f2tf(q1[kc * 8 + tl + 4] * 0.125f);
        }
    }

    float O[8][4];
    #pragma unroll
    for (int nb = 0; nb < 8; nb++)
        #pragma unroll
        for (int i = 0; i < 4; i++) O[nb][i] = 0.0f;
    float m0 = -1e30f, m1 = -1e30f, l0 = 0.0f, l1 = 0.0f;

    for (int t = 0; t < GDIM * (SDIM / KT); t++) {   // 64 KV tiles
        const int j  = t >> 4;
        const int kt = t & 15;
        const float* kb = k + (size_t)j * GSTRIDE + bhoff + (size_t)(kt * KT) * DDIM;
        const float* vb = v + (size_t)j * GSTRIDE + bhoff + (size_t)(kt * KT) * DDIM;

        // ---- load K,V tiles -> smem (tf32-converted), float4 gmem reads ----
        #pragma unroll
        for (int it = 0; it < 4; it++) {
            int vi  = tid + it * 256;         // 0..1023 float4s
            int row = vi >> 4;
            int c0  = (vi & 15) << 2;
            float4 kf = *reinterpret_cast<const float4*>(kb + (size_t)row * DDIM + c0);
            uint4  ku = make_uint4(f2tf(kf.x), f2tf(kf.y), f2tf(kf.z), f2tf(kf.w));
            *reinterpret_cast<uint4*>(Ks + row * KP + c0) = ku;
            float4 vf = *reinterpret_cast<const float4*>(vb + (size_t)row * DDIM + c0);
            uint4  vu = make_uint4(f2tf(vf.x), f2tf(vf.y), f2tf(vf.z), f2tf(vf.w));
            *reinterpret_cast<uint4*>(Vs + row * VP + c0) = vu;
        }
        __syncthreads();

        // ---- GEMM1: S[16x64] = Q @ K^T ----
        // B-frag b0 = (d = kc*8+tl, key = nb*8+tg) = Ks[key*KP + d]
        float S[8][4];
        #pragma unroll
        for (int nb = 0; nb < 8; nb++) {
            S[nb][0] = S[nb][1] = S[nb][2] = S[nb][3] = 0.0f;
            #pragma unroll
            for (int kc = 0; kc < 8; kc++) {
                const uint32_t* kr = Ks + (nb * 8 + tg) * KP + kc * 8 + tl;
                mma_tf32(S[nb], aQ[kc], kr[0], kr[4]);
            }
        }

        // ---- online softmax; rows r0=tg, r1=tg+8; cols 2*tl,2*tl+1 per nb ----
        float mx0 = -1e30f, mx1 = -1e30f;
        #pragma unroll
        for (int nb = 0; nb < 8; nb++) {
            mx0 = fmaxf(mx0, fmaxf(S[nb][0], S[nb][1]));
            mx1 = fmaxf(mx1, fmaxf(S[nb][2], S[nb][3]));
        }
        #pragma unroll
        for (int off = 1; off < 4; off <<= 1) {
            mx0 = fmaxf(mx0, __shfl_xor_sync(0xffffffffu, mx0, off));
            mx1 = fmaxf(mx1, __shfl_xor_sync(0xffffffffu, mx1, off));
        }
        float mn0 = fmaxf(m0, mx0), mn1 = fmaxf(m1, mx1);
        float cr0 = __expf(m0 - mn0), cr1 = __expf(m1 - mn1);
        m0 = mn0; m1 = mn1;
        float s0 = 0.0f, s1 = 0.0f;
        #pragma unroll
        for (int nb = 0; nb < 8; nb++) {
            float p;
            p = __expf(S[nb][0] - mn0); S[nb][0] = p; s0 += p;
            p = __expf(S[nb][1] - mn0); S[nb][1] = p; s0 += p;
            p = __expf(S[nb][2] - mn1); S[nb][2] = p; s1 += p;
            p = __expf(S[nb][3] - mn1); S[nb][3] = p; s1 += p;
        }
        #pragma unroll
        for (int off = 1; off < 4; off <<= 1) {
            s0 += __shfl_xor_sync(0xffffffffu, s0, off);
            s1 += __shfl_xor_sync(0xffffffffu, s1, off);
        }
        l0 = l0 * cr0 + s0;
        l1 = l1 * cr1 + s1;
        #pragma unroll
        for (int nb = 0; nb < 8; nb++) {
            O[nb][0] *= cr0; O[nb][1] *= cr0;
            O[nb][2] *= cr1; O[nb][3] *= cr1;
        }

        // ---- P -> per-warp smem (tf32), C-frag cols are adjacent -> 8B stores ----
        #pragma unroll
        for (int nb = 0; nb < 8; nb++) {
            uint2 p0 = make_uint2(f2tf(S[nb][0]), f2tf(S[nb][1]));
            *reinterpret_cast<uint2*>(Pw + tg * PP + nb * 8 + 2 * tl) = p0;
            uint2 p1 = make_uint2(f2tf(S[nb][2]), f2tf(S[nb][3]));
            *reinterpret_cast<uint2*>(Pw + (tg + 8) * PP + nb * 8 + 2 * tl) = p1;
        }
        __syncwarp();

        // ---- GEMM2: O[16x64] += P @ V ----
        // A-frag from Pw (re-fragmented), B-frag b0 = (key=kc*8+tl, d=nb*8+tg)
        #pragma unroll
        for (int kc = 0; kc < 8; kc++) {
            uint32_t aP[4];
            aP[0] = Pu[tg * PP + kc * 8 + tl];
            aP[1] = Pu[(tg + 8) * PP + kc * 8 + tl];
            aP[2] = Pu[tg * PP + kc * 8 + tl + 4];
            aP[3] = Pu[(tg + 8) * PP + kc * 8 + tl + 4];
            #pragma unroll
            for (int nb = 0; nb < 8; nb++) {
                const uint32_t* vr = Vs + (kc * 8 + tl) * VP + nb * 8 + tg;
                mma_tf32(O[nb], aP[0] ? aP : aP, vr[0], vr[4 * VP]);
            }
        }
        __syncthreads();   // protect Ks/Vs before next tile's loads
    }

    // ---- epilogue: normalize, store (8B vectorized) ----
    {
        float inv0 = 1.0f / l0, inv1 = 1.0f / l1;
        float* ob = out + (size_t)g * GSTRIDE + bhoff
                  + (size_t)(qt * MT + warp * 16 + tg) * DDIM;
        #pragma unroll
        for (int nb = 0; nb < 8; nb++) {
            float2 r0 = make_float2(O[nb][0] * inv0, O[nb][1] * inv0);
            *reinterpret_cast<float2*>(ob + nb * 8 + 2 * tl) = r0;
            float2 r1 = make_float2(O[nb][2] * inv1, O[nb][3] * inv1);
            *reinterpret_cast<float2*>(ob + 8 * DDIM + nb * 8 + 2 * tl) = r1;
        }
    }
}

extern "C" void kernel_launch(void* const* d_in, const int* in_sizes, int n_in,
                              void* d_out, int out_size)
{
    const float* q = (const float*)d_in[0];
    const float* k = (const float*)d_in[1];
    const float* v = (const float*)d_in[2];
    float* out = (float*)d_out;

    const int smem_bytes = SMEM_FLOATS * (int)sizeof(float);  // 70656
    cudaFuncSetAttribute(ring_attn_mma, cudaFuncAttributeMaxDynamicSharedMemorySize,
                         smem_bytes);
    dim3 grid(GDIM * (SDIM / MT), BH);  // (32, 32)
    ring_attn_mma<<<grid, 256, smem_bytes>>>(q, k, v, out);
}

// round 5
// speedup vs baseline: 4.1550x; 1.0525x over previous
#include <cuda_runtime.h>
#include <stdint.h>

// Ring attention == full attention per (b,h) (exact LSE merge is order-free).
// tf32 mma.sync flash attention. CTA = 128 thr = 4 warps; each warp owns 32
// q-rows (two m16 blocks) -> 2x arithmetic intensity vs 16-row warps.
// GEMM1 kc-outer/nb-inner for independent HMMA chains.

#define GDIM 4
#define BH   32
#define SDIM 1024
#define DDIM 64
#define MT   128
#define KT   64

#define KP 68   // K smem pitch: bank = 4*key + d -> conflict-free B-frag loads
#define VP 72   // V smem pitch: bank = 8*key + d -> conflict-free
#define PP 68   // P smem pitch

#define OFF_K 0
#define OFF_V (OFF_K + KT * KP)              // 4352
#define OFF_P (OFF_V + KT * VP)              // 8960
#define SMEM_FLOATS (OFF_P + 4 * 32 * PP)    // 17664 floats = 70656 B

static __device__ __forceinline__ uint32_t f2tf(float f) {
    uint32_t r;
    asm("cvt.rna.tf32.f32 %0, %1;" : "=r"(r) : "f"(f));
    return r;
}

static __device__ __forceinline__ void mma_tf32(float* c, const uint32_t* a,
                                                uint32_t b0, uint32_t b1) {
    asm volatile(
        "mma.sync.aligned.m16n8k8.row.col.f32.tf32.tf32.f32 "
        "{%0,%1,%2,%3}, {%4,%5,%6,%7}, {%8,%9}, {%0,%1,%2,%3};"
        : "+f"(c[0]), "+f"(c[1]), "+f"(c[2]), "+f"(c[3])
        : "r"(a[0]), "r"(a[1]), "r"(a[2]), "r"(a[3]), "r"(b0), "r"(b1));
}

__global__ __launch_bounds__(128, 2) void ring_attn_mma32(
    const float* __restrict__ q,
    const float* __restrict__ k,
    const float* __restrict__ v,
    float* __restrict__ out)
{
    extern __shared__ float sm[];
    uint32_t* Ks = (uint32_t*)(sm + OFF_K);
    uint32_t* Vs = (uint32_t*)(sm + OFF_V);

    const int tid  = threadIdx.x;
    const int warp = tid >> 5;
    const int lane = tid & 31;
    const int tg   = lane >> 2;   // 0..7
    const int tl   = lane & 3;    // 0..3

    float*    Pw = sm + OFF_P + warp * 32 * PP;   // per-warp P buffer [32][PP]
    uint32_t* Pu = (uint32_t*)Pw;

    const int g  = blockIdx.x >> 3;
    const int qt = blockIdx.x & 7;
    const int bh = blockIdx.y;
    const size_t GSTRIDE = (size_t)BH * SDIM * DDIM;
    const size_t bhoff   = (size_t)bh * SDIM * DDIM;

    // ---- Q fragments for 32 rows: aQ[kc][0..3]=block0 (rows tg,tg+8),
    //      aQ[kc][4..7]=block1 (rows 16+tg,24+tg). Held in regs all kernel. ----
    uint32_t aQ[8][8];
    {
        const float* qb = q + (size_t)g * GSTRIDE + bhoff
                        + (size_t)(qt * MT + warp * 32) * DDIM;
        #pragma unroll
        for (int kc = 0; kc < 8; kc++) {
            #pragma unroll
            for (int blk = 0; blk < 2; blk++) {
                const float* r0 = qb + (size_t)(blk * 16 + tg) * DDIM + kc * 8 + tl;
                const float* r1 = r0 + 8 * DDIM;
                aQ[kc][blk * 4 + 0] = f2tf(r0[0] * 0.125f);
                aQ[kc][blk * 4 + 1] = f2tf(r1[0] * 0.125f);
                aQ[kc][blk * 4 + 2] = f2tf(r0[4] * 0.125f);
                aQ[kc][blk * 4 + 3] = f2tf(r1[4] * 0.125f);
            }
        }
    }

    float O[8][8];
    #pragma unroll
    for (int nb = 0; nb < 8; nb++)
        #pragma unroll
        for (int i = 0; i < 8; i++) O[nb][i] = 0.0f;
    // 4 row-sets: rs0=rows tg, rs1=tg+8, rs2=16+tg, rs3=24+tg
    float m[4], l[4];
    #pragma unroll
    for (int rs = 0; rs < 4; rs++) { m[rs] = -1e30f; l[rs] = 0.0f; }

    for (int t = 0; t < GDIM * (SDIM / KT); t++) {   // 64 KV tiles
        const int j  = t >> 4;
        const int kt = t & 15;
        const float* kb = k + (size_t)j * GSTRIDE + bhoff + (size_t)(kt * KT) * DDIM;
        const float* vb = v + (size_t)j * GSTRIDE + bhoff + (size_t)(kt * KT) * DDIM;

        // ---- cooperative K,V tile load -> smem (tf32), float4 gmem reads ----
        #pragma unroll
        for (int it = 0; it < 8; it++) {
            int vi  = tid + it * 128;          // 0..1023 float4s
            int row = vi >> 4;
            int c0  = (vi & 15) << 2;
            float4 kf = *reinterpret_cast<const float4*>(kb + (size_t)row * DDIM + c0);
            uint4  ku = make_uint4(f2tf(kf.x), f2tf(kf.y), f2tf(kf.z), f2tf(kf.w));
            *reinterpret_cast<uint4*>(Ks + row * KP + c0) = ku;
            float4 vf = *reinterpret_cast<const float4*>(vb + (size_t)row * DDIM + c0);
            uint4  vu = make_uint4(f2tf(vf.x), f2tf(vf.y), f2tf(vf.z), f2tf(vf.w));
            *reinterpret_cast<uint4*>(Vs + row * VP + c0) = vu;
        }
        __syncthreads();

        // ---- GEMM1: S[32x64] = Q @ K^T; kc outer, nb inner (indep chains) ----
        float S[8][8];
        #pragma unroll
        for (int nb = 0; nb < 8; nb++)
            #pragma unroll
            for (int i = 0; i < 8; i++) S[nb][i] = 0.0f;

        #pragma unroll
        for (int kc = 0; kc < 8; kc++) {
            #pragma unroll
            for (int nb = 0; nb < 8; nb++) {
                const uint32_t* kr = Ks + (nb * 8 + tg) * KP + kc * 8 + tl;
                uint32_t b0 = kr[0], b1 = kr[4];
                mma_tf32(S[nb] + 0, aQ[kc] + 0, b0, b1);
                mma_tf32(S[nb] + 4, aQ[kc] + 4, b0, b1);
            }
        }

        // ---- online softmax over 4 row-sets ----
        float mx[4] = {-1e30f, -1e30f, -1e30f, -1e30f};
        #pragma unroll
        for (int nb = 0; nb < 8; nb++)
            #pragma unroll
            for (int rs = 0; rs < 4; rs++)
                mx[rs] = fmaxf(mx[rs], fmaxf(S[nb][2 * rs], S[nb][2 * rs + 1]));
        #pragma unroll
        for (int off = 1; off < 4; off <<= 1)
            #pragma unroll
            for (int rs = 0; rs < 4; rs++)
                mx[rs] = fmaxf(mx[rs], __shfl_xor_sync(0xffffffffu, mx[rs], off));

        float cr[4], sl[4];
        #pragma unroll
        for (int rs = 0; rs < 4; rs++) {
            float mn = fmaxf(m[rs], mx[rs]);
            cr[rs] = __expf(m[rs] - mn);
            m[rs] = mn;
            sl[rs] = 0.0f;
        }
        #pragma unroll
        for (int nb = 0; nb < 8; nb++)
            #pragma unroll
            for (int rs = 0; rs < 4; rs++) {
                float p0 = __expf(S[nb][2 * rs]     - m[rs]);
                float p1 = __expf(S[nb][2 * rs + 1] - m[rs]);
                S[nb][2 * rs]     = p0;
                S[nb][2 * rs + 1] = p1;
                sl[rs] += p0 + p1;
            }
        #pragma unroll
        for (int off = 1; off < 4; off <<= 1)
            #pragma unroll
            for (int rs = 0; rs < 4; rs++)
                sl[rs] += __shfl_xor_sync(0xffffffffu, sl[rs], off);
        #pragma unroll
        for (int rs = 0; rs < 4; rs++)
            l[rs] = l[rs] * cr[rs] + sl[rs];
        #pragma unroll
        for (int nb = 0; nb < 8; nb++)
            #pragma unroll
            for (int rs = 0; rs < 4; rs++) {
                O[nb][2 * rs]     *= cr[rs];
                O[nb][2 * rs + 1] *= cr[rs];
            }

        // ---- P -> per-warp smem (tf32), C-frag col pairs -> STS.64 ----
        #pragma unroll
        for (int nb = 0; nb < 8; nb++) {
            #pragma unroll
            for (int blk = 0; blk < 2; blk++) {
                uint2 p0 = make_uint2(f2tf(S[nb][blk * 4 + 0]),
                                      f2tf(S[nb][blk * 4 + 1]));
                *reinterpret_cast<uint2*>(Pw + (blk * 16 + tg) * PP + nb * 8 + 2 * tl) = p0;
                uint2 p1 = make_uint2(f2tf(S[nb][blk * 4 + 2]),
                                      f2tf(S[nb][blk * 4 + 3]));
                *reinterpret_cast<uint2*>(Pw + (blk * 16 + tg + 8) * PP + nb * 8 + 2 * tl) = p1;
            }
        }
        __syncwarp();

        // ---- GEMM2: O[32x64] += P @ V ----
        #pragma unroll
        for (int kc = 0; kc < 8; kc++) {
            uint32_t aP[8];
            #pragma unroll
            for (int blk = 0; blk < 2; blk++) {
                aP[blk * 4 + 0] = Pu[(blk * 16 + tg)     * PP + kc * 8 + tl];
                aP[blk * 4 + 1] = Pu[(blk * 16 + tg + 8) * PP + kc * 8 + tl];
                aP[blk * 4 + 2] = Pu[(blk * 16 + tg)     * PP + kc * 8 + tl + 4];
                aP[blk * 4 + 3] = Pu[(blk * 16 + tg + 8) * PP + kc * 8 + tl + 4];
            }
            #pragma unroll
            for (int nb = 0; nb < 8; nb++) {
                const uint32_t* vr = Vs + (kc * 8 + tl) * VP + nb * 8 + tg;
                uint32_t b0 = vr[0], b1 = vr[4 * VP];
                mma_tf32(O[nb] + 0, aP + 0, b0, b1);
                mma_tf32(O[nb] + 4, aP + 4, b0, b1);
            }
        }
        __syncthreads();   // protect Ks/Vs before next tile's loads
    }

    // ---- epilogue: normalize, store (8B vectorized) ----
    {
        float inv[4];
        #pragma unroll
        for (int rs = 0; rs < 4; rs++) inv[rs] = 1.0f / l[rs];
        float* ob = out + (size_t)g * GSTRIDE + bhoff
                  + (size_t)(qt * MT + warp * 32) * DDIM;
        #pragma unroll
        for (int rs = 0; rs < 4; rs++) {
            int row = ((rs & 1) ? tg + 8 : tg) + (rs >> 1) * 16;
            #pragma unroll
            for (int nb = 0; nb < 8; nb++) {
                float2 r = make_float2(O[nb][2 * rs] * inv[rs],
                                       O[nb][2 * rs + 1] * inv[rs]);
                *reinterpret_cast<float2*>(ob + (size_t)row * DDIM + nb * 8 + 2 * tl) = r;
            }
        }
    }
}

extern "C" void kernel_launch(void* const* d_in, const int* in_sizes, int n_in,
                              void* d_out, int out_size)
{
    const float* q = (const float*)d_in[0];
    const float* k = (const float*)d_in[1];
    const float* v = (const float*)d_in[2];
    float* out = (float*)d_out;

    const int smem_bytes = SMEM_FLOATS * (int)sizeof(float);  // 70656
    cudaFuncSetAttribute(ring_attn_mma32, cudaFuncAttributeMaxDynamicSharedMemorySize,
                         smem_bytes);
    dim3 grid(GDIM * (SDIM / MT), BH);  // (32, 32)
    ring_attn_mma32<<<grid, 128, smem_bytes>>>(q, k, v, out);
}